// round 5
// baseline (speedup 1.0000x reference)
#include <cuda_runtime.h>
#include <cuda_bf16.h>
#include <cstdint>

// Problem shape
#define M_TOTAL 16384
#define N_TOTAL 4096
#define K_TOTAL 4096
#define KK      (2 * K_TOTAL)   // 8192: hi | lo split along K

// GEMM tiling (bf16 elements)
#define BM 128
#define BN 256
#define BK 64
#define STAGES 4
#define ITERS (KK / BK)         // 128

#define A_BYTES   (BM * BK * 2)          // 16384
#define B_BYTES   (BN * BK * 2)          // 32768
#define STG_BYTES (A_BYTES + B_BYTES)    // 49152
#define SMEM_TOTAL (STAGES * STG_BYTES)  // 196608

// Static scratch (no allocs allowed). A: [M, 8192] bf16 (cols 0..4095 = hi,
// 4096..8191 = lo). W: [N, 4096] bf16 (exact: weights are ints in [0,127]).
__device__ __align__(1024) __nv_bfloat16 g_A[(size_t)M_TOTAL * KK];
__device__ __align__(1024) __nv_bfloat16 g_W[(size_t)N_TOTAL * K_TOTAL];

// ---------------- prologue: conversion kernels ----------------

__global__ void convert_x(const float4* __restrict__ x, int n4) {
    int i = blockIdx.x * blockDim.x + threadIdx.x;
    if (i >= n4) return;
    float4 v = x[i];
    int flat = i << 2;                 // element index, < 2^27
    int m = flat >> 12;                // / 4096
    int k = flat & 4095;

    __nv_bfloat16 h0 = __float2bfloat16(v.x);
    __nv_bfloat16 h1 = __float2bfloat16(v.y);
    __nv_bfloat16 h2 = __float2bfloat16(v.z);
    __nv_bfloat16 h3 = __float2bfloat16(v.w);
    __nv_bfloat16 l0 = __float2bfloat16(v.x - __bfloat162float(h0));
    __nv_bfloat16 l1 = __float2bfloat16(v.y - __bfloat162float(h1));
    __nv_bfloat16 l2 = __float2bfloat16(v.z - __bfloat162float(h2));
    __nv_bfloat16 l3 = __float2bfloat16(v.w - __bfloat162float(h3));

    uint2 hv, lv;
    hv.x = (uint32_t)__bfloat16_as_ushort(h0) | ((uint32_t)__bfloat16_as_ushort(h1) << 16);
    hv.y = (uint32_t)__bfloat16_as_ushort(h2) | ((uint32_t)__bfloat16_as_ushort(h3) << 16);
    lv.x = (uint32_t)__bfloat16_as_ushort(l0) | ((uint32_t)__bfloat16_as_ushort(l1) << 16);
    lv.y = (uint32_t)__bfloat16_as_ushort(l2) | ((uint32_t)__bfloat16_as_ushort(l3) << 16);

    size_t base = (size_t)m * KK + k;
    *(uint2*)&g_A[base]          = hv;
    *(uint2*)&g_A[base + K_TOTAL] = lv;
}

__global__ void convert_w(const int4* __restrict__ wq, int n4) {
    int i = blockIdx.x * blockDim.x + threadIdx.x;
    if (i >= n4) return;
    int4 v = wq[i];
    __nv_bfloat16 b0 = __float2bfloat16((float)v.x);
    __nv_bfloat16 b1 = __float2bfloat16((float)v.y);
    __nv_bfloat16 b2 = __float2bfloat16((float)v.z);
    __nv_bfloat16 b3 = __float2bfloat16((float)v.w);
    uint2 pv;
    pv.x = (uint32_t)__bfloat16_as_ushort(b0) | ((uint32_t)__bfloat16_as_ushort(b1) << 16);
    pv.y = (uint32_t)__bfloat16_as_ushort(b2) | ((uint32_t)__bfloat16_as_ushort(b3) << 16);
    *(uint2*)&g_W[(size_t)i * 4] = pv;
}

// ---------------- GEMM ----------------

__device__ __forceinline__ uint32_t lds32(uint32_t addr) {
    uint32_t v;
    asm volatile("ld.shared.b32 %0, [%1];" : "=r"(v) : "r"(addr));
    return v;
}

__device__ __forceinline__ void cp16(uint32_t smem_dst, const void* gsrc) {
    asm volatile("cp.async.cg.shared.global [%0], [%1], 16;"
                 :: "r"(smem_dst), "l"(gsrc));
}

__device__ __forceinline__ void cp_commit() {
    asm volatile("cp.async.commit_group;" ::: "memory");
}

__device__ __forceinline__ void mma_bf16(float* c, const uint32_t* a, const uint32_t* b) {
    asm volatile(
        "mma.sync.aligned.m16n8k16.row.col.f32.bf16.bf16.f32 "
        "{%0,%1,%2,%3}, {%4,%5,%6,%7}, {%8,%9}, {%0,%1,%2,%3};"
        : "+f"(c[0]), "+f"(c[1]), "+f"(c[2]), "+f"(c[3])
        : "r"(a[0]), "r"(a[1]), "r"(a[2]), "r"(a[3]), "r"(b[0]), "r"(b[1]));
}

__global__ void __launch_bounds__(256, 1)
gemm_split_bf16(const float* __restrict__ scale,
                const float* __restrict__ bias,
                float* __restrict__ out)
{
    extern __shared__ __align__(1024) char smem[];
    const uint32_t sb = (uint32_t)__cvta_generic_to_shared(smem);

    const int tid  = threadIdx.x;
    const int lane = tid & 31;
    const int wid  = tid >> 5;
    const int wm   = wid & 1;          // 2 warp rows (M)
    const int wn   = wid >> 1;         // 4 warp cols (N)
    const int m_cta = blockIdx.y * BM;
    const int n_cta = blockIdx.x * BN;

    const int r_lo = lane >> 2;        // 0..7
    const int kb   = (lane & 3) * 4;   // byte offset of bf16 pair in k
    const int xr   = r_lo * 16;        // 128B XOR swizzle term

    // producer thread mapping
    const int a_row0 = tid >> 3;       // A: 128 rows x 8 chunks, 4 iters
    const int b_row0 = tid >> 3;       // B: 256 rows x 8 chunks, 8 iters
    const int chnk   = tid & 7;
    const uint32_t sw_st = (uint32_t)((chnk * 16));

    auto load_slab = [&](int kit, int s) {
        char* dummy = smem; (void)dummy;
        const uint32_t st = sb + s * STG_BYTES;
        const __nv_bfloat16* aG = g_A + (size_t)(m_cta) * KK + kit * BK;
        const __nv_bfloat16* bG = g_W + (size_t)(n_cta) * K_TOTAL + (kit & 63) * BK;
        #pragma unroll
        for (int j = 0; j < 4; j++) {
            int row = a_row0 + j * 32;
            uint32_t dst = st + row * 128 + (sw_st ^ ((row & 7) * 16));
            cp16(dst, aG + (size_t)row * KK + chnk * 8);
        }
        #pragma unroll
        for (int j = 0; j < 8; j++) {
            int row = b_row0 + j * 32;
            uint32_t dst = st + A_BYTES + row * 128 + (sw_st ^ ((row & 7) * 16));
            cp16(dst, bG + (size_t)row * K_TOTAL + chnk * 8);
        }
    };

    float acc[4][8][4];
    #pragma unroll
    for (int mt = 0; mt < 4; mt++)
        #pragma unroll
        for (int nt = 0; nt < 8; nt++)
            #pragma unroll
            for (int j = 0; j < 4; j++)
                acc[mt][nt][j] = 0.0f;

    // prologue: fill 3 stages
    #pragma unroll
    for (int s = 0; s < STAGES - 1; s++) {
        load_slab(s, s);
        cp_commit();
    }

    for (int i = 0; i < ITERS; i++) {
        asm volatile("cp.async.wait_group %0;" :: "n"(STAGES - 2) : "memory");
        __syncthreads();

        if (i + STAGES - 1 < ITERS)
            load_slab(i + STAGES - 1, (i + STAGES - 1) & (STAGES - 1));
        cp_commit();

        const uint32_t abase = sb + (i & (STAGES - 1)) * STG_BYTES;
        const uint32_t bbase = abase + A_BYTES;

        #pragma unroll
        for (int ks = 0; ks < 4; ks++) {
            const int k0 = ks * 32 + kb;
            uint32_t af[4][4];
            #pragma unroll
            for (int mt = 0; mt < 4; mt++) {
                const uint32_t rb = abase + (wm * 64 + mt * 16 + r_lo) * 128;
                af[mt][0] = lds32(rb             + ((k0)      ^ xr));
                af[mt][1] = lds32(rb + 8 * 128   + ((k0)      ^ xr));
                af[mt][2] = lds32(rb             + ((k0 + 16) ^ xr));
                af[mt][3] = lds32(rb + 8 * 128   + ((k0 + 16) ^ xr));
            }
            uint32_t bf[8][2];
            #pragma unroll
            for (int nt = 0; nt < 8; nt++) {
                const uint32_t rb = bbase + (wn * 64 + nt * 8 + r_lo) * 128;
                bf[nt][0] = lds32(rb + ((k0)      ^ xr));
                bf[nt][1] = lds32(rb + ((k0 + 16) ^ xr));
            }
            #pragma unroll
            for (int mt = 0; mt < 4; mt++)
                #pragma unroll
                for (int nt = 0; nt < 8; nt++)
                    mma_bf16(acc[mt][nt], af[mt], bf[nt]);
        }
    }

    // epilogue: y = scale * acc + bias
    const float sc = __ldg(scale);
    #pragma unroll
    for (int mt = 0; mt < 4; mt++) {
        const int m0 = m_cta + wm * 64 + mt * 16 + r_lo;
        #pragma unroll
        for (int nt = 0; nt < 8; nt++) {
            const int n0 = n_cta + wn * 64 + nt * 8 + (lane & 3) * 2;
            const float b0 = __ldg(bias + n0);
            const float b1 = __ldg(bias + n0 + 1);
            float2 v0, v1;
            v0.x = fmaf(sc, acc[mt][nt][0], b0);
            v0.y = fmaf(sc, acc[mt][nt][1], b1);
            v1.x = fmaf(sc, acc[mt][nt][2], b0);
            v1.y = fmaf(sc, acc[mt][nt][3], b1);
            *(float2*)(out + (size_t)m0 * N_TOTAL + n0)       = v0;
            *(float2*)(out + (size_t)(m0 + 8) * N_TOTAL + n0) = v1;
        }
    }
}

// ---------------- host ----------------

extern "C" void kernel_launch(void* const* d_in, const int* in_sizes, int n_in,
                              void* d_out, int out_size)
{
    const float* x     = (const float*)d_in[0];
    const int*   wq    = (const int*)  d_in[1];
    const float* scale = (const float*)d_in[2];
    const float* bias  = (const float*)d_in[3];
    float*       out   = (float*)d_out;

    {
        int n4 = (M_TOTAL * K_TOTAL) / 4;       // 16,777,216
        convert_x<<<n4 / 256, 256>>>((const float4*)x, n4);
    }
    {
        int n4 = (N_TOTAL * K_TOTAL) / 4;       // 4,194,304
        convert_w<<<n4 / 256, 256>>>((const int4*)wq, n4);
    }

    static bool attr_set = false;
    if (!attr_set) {
        cudaFuncSetAttribute(gemm_split_bf16,
                             cudaFuncAttributeMaxDynamicSharedMemorySize, SMEM_TOTAL);
        attr_set = true;
    }

    dim3 grid(N_TOTAL / BN, M_TOTAL / BM);      // (16, 128)
    gemm_split_bf16<<<grid, 256, SMEM_TOTAL>>>(scale, bias, out);
}

// round 7
// speedup vs baseline: 1.9495x; 1.9495x over previous
#include <cuda_runtime.h>
#include <cuda_fp16.h>
#include <cstdint>

// Problem shape
#define M_TOTAL 16384
#define N_TOTAL 4096
#define K_TOTAL 4096

// GEMM tiling (fp16 elements)
#define BM 128
#define BN 256
#define BK 64
#define STAGES 4
#define ITERS (K_TOTAL / BK)             // 64

#define A_BYTES   (BM * BK * 2)          // 16384
#define B_BYTES   (BN * BK * 2)          // 32768
#define STG_BYTES (A_BYTES + B_BYTES)    // 49152
#define SMEM_TOTAL (STAGES * STG_BYTES)  // 196608

// Static scratch (no allocs). A: [M,4096] fp16 copy of x. W: [N,4096] fp16 (exact).
__device__ __align__(1024) __half g_A[(size_t)M_TOTAL * K_TOTAL];
__device__ __align__(1024) __half g_W[(size_t)N_TOTAL * K_TOTAL];

// ---------------- prologue: conversion kernels ----------------

__global__ void convert_x(const float4* __restrict__ x, int n4) {
    int i = blockIdx.x * blockDim.x + threadIdx.x;
    if (i >= n4) return;
    float4 v = x[i];
    __half2 h01 = __floats2half2_rn(v.x, v.y);
    __half2 h23 = __floats2half2_rn(v.z, v.w);
    uint2 pv;
    pv.x = *(uint32_t*)&h01;
    pv.y = *(uint32_t*)&h23;
    *(uint2*)&g_A[(size_t)i * 4] = pv;
}

__global__ void convert_w(const int4* __restrict__ wq, int n4) {
    int i = blockIdx.x * blockDim.x + threadIdx.x;
    if (i >= n4) return;
    int4 v = wq[i];
    __half2 h01 = __floats2half2_rn((float)v.x, (float)v.y);
    __half2 h23 = __floats2half2_rn((float)v.z, (float)v.w);
    uint2 pv;
    pv.x = *(uint32_t*)&h01;
    pv.y = *(uint32_t*)&h23;
    *(uint2*)&g_W[(size_t)i * 4] = pv;
}

// ---------------- GEMM ----------------

__device__ __forceinline__ void cp16(uint32_t smem_dst, const void* gsrc) {
    asm volatile("cp.async.cg.shared.global [%0], [%1], 16;"
                 :: "r"(smem_dst), "l"(gsrc));
}

__device__ __forceinline__ void cp_commit() {
    asm volatile("cp.async.commit_group;" ::: "memory");
}

__device__ __forceinline__ void ldsm_x4(uint32_t* r, uint32_t addr) {
    asm volatile("ldmatrix.sync.aligned.m8n8.x4.shared.b16 {%0,%1,%2,%3}, [%4];"
                 : "=r"(r[0]), "=r"(r[1]), "=r"(r[2]), "=r"(r[3]) : "r"(addr));
}

__device__ __forceinline__ void mma_f16(float* c, const uint32_t* a, const uint32_t* b) {
    asm volatile(
        "mma.sync.aligned.m16n8k16.row.col.f32.f16.f16.f32 "
        "{%0,%1,%2,%3}, {%4,%5,%6,%7}, {%8,%9}, {%0,%1,%2,%3};"
        : "+f"(c[0]), "+f"(c[1]), "+f"(c[2]), "+f"(c[3])
        : "r"(a[0]), "r"(a[1]), "r"(a[2]), "r"(a[3]), "r"(b[0]), "r"(b[1]));
}

__global__ void __launch_bounds__(256, 1)
gemm_f16(const float* __restrict__ scale,
         const float* __restrict__ bias,
         float* __restrict__ out)
{
    extern __shared__ __align__(1024) char smem[];
    const uint32_t sb = (uint32_t)__cvta_generic_to_shared(smem);

    const int tid  = threadIdx.x;
    const int lane = tid & 31;
    const int wid  = tid >> 5;
    const int wm   = wid & 1;          // 2 warp rows (M), 64 rows each
    const int wn   = wid >> 1;         // 4 warp cols (N), 64 cols each
    const int m_cta = blockIdx.y * BM;
    const int n_cta = blockIdx.x * BN;

    // ---- ldmatrix lane address precompute ----
    // A (16x16 tiles, x4): lanes 0-15 -> rows m0..m15 @k0, lanes 16-31 -> same rows @k0+8
    const int arow  = lane & 15;
    const int ahalf = lane >> 4;                   // +16 bytes for k0+8
    const uint32_t a_xr = (uint32_t)((arow & 7) * 16);
    uint32_t a_off[4];
    #pragma unroll
    for (int mt = 0; mt < 4; mt++)
        a_off[mt] = (uint32_t)((wm * 64 + mt * 16 + arow) * 128);

    // B (two n8 tiles x two k-halves per x4): lanes 0-7 n0..7@k0, 8-15 n0..7@k0+8,
    //                                         16-23 n8..15@k0, 24-31 n8..15@k0+8
    const int brow_in = lane & 7;
    const int bkh     = (lane >> 3) & 1;
    const int bn2     = lane >> 4;
    const uint32_t b_xr = (uint32_t)(brow_in * 16);
    uint32_t b_off[4];
    #pragma unroll
    for (int nt2 = 0; nt2 < 4; nt2++)
        b_off[nt2] = (uint32_t)((wn * 64 + nt2 * 16 + bn2 * 8 + brow_in) * 128);

    // ---- producer mapping (cp.async) ----
    const int prow = tid >> 3;         // 32 rows per pass
    const int chnk = tid & 7;          // 8 x 16B chunks per 128B row
    const uint32_t sw_st = (uint32_t)(chnk * 16);

    auto load_slab = [&](int kit, int s) {
        const uint32_t st = sb + s * STG_BYTES;
        const __half* aG = g_A + (size_t)m_cta * K_TOTAL + kit * BK;
        const __half* bG = g_W + (size_t)n_cta * K_TOTAL + kit * BK;
        #pragma unroll
        for (int j = 0; j < 4; j++) {
            int row = prow + j * 32;
            uint32_t dst = st + row * 128 + (sw_st ^ ((row & 7) * 16));
            cp16(dst, aG + (size_t)row * K_TOTAL + chnk * 8);
        }
        #pragma unroll
        for (int j = 0; j < 8; j++) {
            int row = prow + j * 32;
            uint32_t dst = st + A_BYTES + row * 128 + (sw_st ^ ((row & 7) * 16));
            cp16(dst, bG + (size_t)row * K_TOTAL + chnk * 8);
        }
    };

    float acc[4][8][4];
    #pragma unroll
    for (int mt = 0; mt < 4; mt++)
        #pragma unroll
        for (int nt = 0; nt < 8; nt++)
            #pragma unroll
            for (int j = 0; j < 4; j++)
                acc[mt][nt][j] = 0.0f;

    #pragma unroll
    for (int s = 0; s < STAGES - 1; s++) {
        load_slab(s, s);
        cp_commit();
    }

    uint32_t af[2][4][4];
    uint32_t bf[2][8][2];

    for (int i = 0; i < ITERS; i++) {
        asm volatile("cp.async.wait_group %0;" :: "n"(STAGES - 2) : "memory");
        __syncthreads();

        if (i + STAGES - 1 < ITERS)
            load_slab(i + STAGES - 1, (i + STAGES - 1) & (STAGES - 1));
        cp_commit();

        const uint32_t abase = sb + (i & (STAGES - 1)) * STG_BYTES;
        const uint32_t bbase = abase + A_BYTES;

        // load fragments for ks=0 into buffer 0
        {
            const uint32_t acol = (uint32_t)(ahalf * 16);
            #pragma unroll
            for (int mt = 0; mt < 4; mt++)
                ldsm_x4(af[0][mt], abase + a_off[mt] + (acol ^ a_xr));
            const uint32_t bcol = (uint32_t)(bkh * 16);
            #pragma unroll
            for (int nt2 = 0; nt2 < 4; nt2++) {
                uint32_t r[4];
                ldsm_x4(r, bbase + b_off[nt2] + (bcol ^ b_xr));
                bf[0][2 * nt2][0] = r[0]; bf[0][2 * nt2][1] = r[1];
                bf[0][2 * nt2 + 1][0] = r[2]; bf[0][2 * nt2 + 1][1] = r[3];
            }
        }

        #pragma unroll
        for (int ks = 0; ks < 4; ks++) {
            const int cur = ks & 1, nxt = cur ^ 1;
            if (ks < 3) {   // prefetch next k-sub-step while computing this one
                const uint32_t acol = (uint32_t)((ks + 1) * 32 + ahalf * 16);
                #pragma unroll
                for (int mt = 0; mt < 4; mt++)
                    ldsm_x4(af[nxt][mt], abase + a_off[mt] + (acol ^ a_xr));
                const uint32_t bcol = (uint32_t)((ks + 1) * 32 + bkh * 16);
                #pragma unroll
                for (int nt2 = 0; nt2 < 4; nt2++) {
                    uint32_t r[4];
                    ldsm_x4(r, bbase + b_off[nt2] + (bcol ^ b_xr));
                    bf[nxt][2 * nt2][0] = r[0]; bf[nxt][2 * nt2][1] = r[1];
                    bf[nxt][2 * nt2 + 1][0] = r[2]; bf[nxt][2 * nt2 + 1][1] = r[3];
                }
            }
            #pragma unroll
            for (int mt = 0; mt < 4; mt++)
                #pragma unroll
                for (int nt = 0; nt < 8; nt++)
                    mma_f16(acc[mt][nt], af[cur][mt], bf[cur][nt]);
        }
    }

    // epilogue: y = scale * acc + bias
    const float sc = __ldg(scale);
    const int r_lo = lane >> 2;
    #pragma unroll
    for (int mt = 0; mt < 4; mt++) {
        const int m0 = m_cta + wm * 64 + mt * 16 + r_lo;
        #pragma unroll
        for (int nt = 0; nt < 8; nt++) {
            const int n0 = n_cta + wn * 64 + nt * 8 + (lane & 3) * 2;
            const float b0 = __ldg(bias + n0);
            const float b1 = __ldg(bias + n0 + 1);
            float2 v0, v1;
            v0.x = fmaf(sc, acc[mt][nt][0], b0);
            v0.y = fmaf(sc, acc[mt][nt][1], b1);
            v1.x = fmaf(sc, acc[mt][nt][2], b0);
            v1.y = fmaf(sc, acc[mt][nt][3], b1);
            *(float2*)(out + (size_t)m0 * N_TOTAL + n0)       = v0;
            *(float2*)(out + (size_t)(m0 + 8) * N_TOTAL + n0) = v1;
        }
    }
}

// ---------------- host ----------------

extern "C" void kernel_launch(void* const* d_in, const int* in_sizes, int n_in,
                              void* d_out, int out_size)
{
    const float* x     = (const float*)d_in[0];
    const int*   wq    = (const int*)  d_in[1];
    const float* scale = (const float*)d_in[2];
    const float* bias  = (const float*)d_in[3];
    float*       out   = (float*)d_out;

    {
        int n4 = (M_TOTAL * K_TOTAL) / 4;       // 16,777,216
        convert_x<<<n4 / 256, 256>>>((const float4*)x, n4);
    }
    {
        int n4 = (N_TOTAL * K_TOTAL) / 4;       // 4,194,304
        convert_w<<<n4 / 256, 256>>>((const int4*)wq, n4);
    }

    static bool attr_set = false;
    if (!attr_set) {
        cudaFuncSetAttribute(gemm_f16,
                             cudaFuncAttributeMaxDynamicSharedMemorySize, SMEM_TOTAL);
        attr_set = true;
    }

    dim3 grid(N_TOTAL / BN, M_TOTAL / BM);      // (16, 128)
    gemm_f16<<<grid, 256, SMEM_TOTAL>>>(scale, bias, out);
}